// round 1
// baseline (speedup 1.0000x reference)
#include <cuda_runtime.h>

#define NP  500000
#define NC  1000
#define DIM 128

// Scratch (no allocations allowed -> __device__ globals)
__device__ int g_is64;
__device__ int g_counts[NC];
__device__ int g_offsets[NC];
__device__ int g_cursor[NC];
__device__ int g_sorted[NP];

// ---------------------------------------------------------------------------
// Kernel 0: zero per-class counts; thread 0 probes y dtype (int64 vs int32).
// If y is int64 (little-endian), every odd 32-bit word of the first 256 words
// is 0 (classes < 1000 << 2^31). For int32 input, 128 consecutive odd words
// all being zero has probability ~1000^-128.
// ---------------------------------------------------------------------------
__global__ void detect_zero_kernel(const int* __restrict__ y32) {
    int t = blockIdx.x * blockDim.x + threadIdx.x;
    if (t < NC) g_counts[t] = 0;
    if (t == 0) {
        int all0 = 1;
        #pragma unroll
        for (int i = 1; i < 256; i += 2) all0 &= (y32[i] == 0);
        g_is64 = all0;  // 1 -> stride-2 int32 reads (low word of int64)
    }
}

// ---------------------------------------------------------------------------
// Kernel 1: histogram of classes, privatized in shared memory.
// ---------------------------------------------------------------------------
__global__ void __launch_bounds__(256) hist_kernel(const int* __restrict__ y32) {
    __shared__ int sh[NC];
    for (int i = threadIdx.x; i < NC; i += blockDim.x) sh[i] = 0;
    __syncthreads();
    const int shift  = g_is64;
    const int stride = gridDim.x * blockDim.x;
    for (int i = blockIdx.x * blockDim.x + threadIdx.x; i < NP; i += stride)
        atomicAdd(&sh[y32[i << shift]], 1);
    __syncthreads();
    for (int i = threadIdx.x; i < NC; i += blockDim.x) {
        int v = sh[i];
        if (v) atomicAdd(&g_counts[i], v);
    }
}

// ---------------------------------------------------------------------------
// Kernel 2: exclusive prefix scan over 1000 counts (single block, Hillis-Steele).
// ---------------------------------------------------------------------------
__global__ void scan_kernel() {
    __shared__ int sh[1024];
    int t = threadIdx.x;
    int v = (t < NC) ? g_counts[t] : 0;
    sh[t] = v;
    __syncthreads();
    for (int off = 1; off < 1024; off <<= 1) {
        int add = (t >= off) ? sh[t - off] : 0;
        __syncthreads();
        sh[t] += add;
        __syncthreads();
    }
    if (t < NC) {
        int excl = sh[t] - v;
        g_offsets[t] = excl;
        g_cursor[t]  = excl;
    }
}

// ---------------------------------------------------------------------------
// Kernel 3: scatter point indices into class-sorted order.
// 500k int atomics spread over 1000 counters across ~184 LTS slices -> cheap.
// ---------------------------------------------------------------------------
__global__ void __launch_bounds__(256) scatter_kernel(const int* __restrict__ y32) {
    const int shift  = g_is64;
    const int stride = gridDim.x * blockDim.x;
    for (int i = blockIdx.x * blockDim.x + threadIdx.x; i < NP; i += stride) {
        int c   = y32[i << shift];
        int pos = atomicAdd(&g_cursor[c], 1);
        g_sorted[pos] = i;
    }
}

// ---------------------------------------------------------------------------
// Kernel 4: one block per class. 8 row-groups x 32 lanes; each lane owns 4 dims
// (float4). Rows are 512B contiguous -> fully coalesced. Index prefetch x4 for
// memory-level parallelism. Reduce groups through shared, then CMA update.
// ---------------------------------------------------------------------------
__global__ void __launch_bounds__(256) mean_kernel(
    const float* __restrict__ x,
    const float* __restrict__ centers,
    const float* __restrict__ counter,
    float*       __restrict__ out)
{
    const int c    = blockIdx.x;
    const int cnt  = g_counts[c];
    const int off  = g_offsets[c];
    const int lane = threadIdx.x & 31;
    const int grp  = threadIdx.x >> 5;

    float4 acc = make_float4(0.f, 0.f, 0.f, 0.f);

    int r = grp;
    // main loop: 4 rows in flight per thread
    for (; r + 24 < cnt; r += 32) {
        int i0 = g_sorted[off + r];
        int i1 = g_sorted[off + r + 8];
        int i2 = g_sorted[off + r + 16];
        int i3 = g_sorted[off + r + 24];
        float4 v0 = ((const float4*)(x + (size_t)i0 * DIM))[lane];
        float4 v1 = ((const float4*)(x + (size_t)i1 * DIM))[lane];
        float4 v2 = ((const float4*)(x + (size_t)i2 * DIM))[lane];
        float4 v3 = ((const float4*)(x + (size_t)i3 * DIM))[lane];
        acc.x += v0.x + v1.x + v2.x + v3.x;
        acc.y += v0.y + v1.y + v2.y + v3.y;
        acc.z += v0.z + v1.z + v2.z + v3.z;
        acc.w += v0.w + v1.w + v2.w + v3.w;
    }
    // tail
    for (; r < cnt; r += 8) {
        int i = g_sorted[off + r];
        float4 v = ((const float4*)(x + (size_t)i * DIM))[lane];
        acc.x += v.x; acc.y += v.y; acc.z += v.z; acc.w += v.w;
    }

    __shared__ float4 sh[8][32];
    sh[grp][lane] = acc;
    __syncthreads();

    if (grp == 0) {
        float4 s = sh[0][lane];
        #pragma unroll
        for (int g = 1; g < 8; g++) {
            float4 v = sh[g][lane];
            s.x += v.x; s.y += v.y; s.z += v.z; s.w += v.w;
        }
        float4 cv = ((const float4*)(centers + c * DIM))[lane];
        float4 o;
        if (cnt > 0) {
            float ctr = counter[0];
            float inv = 1.0f / (ctr + 1.0f);
            float rn  = 1.0f / (float)cnt;
            o.x = (s.x * rn + cv.x * ctr) * inv;
            o.y = (s.y * rn + cv.y * ctr) * inv;
            o.z = (s.z * rn + cv.z * ctr) * inv;
            o.w = (s.w * rn + cv.w * ctr) * inv;
        } else {
            o = cv;  // class absent from batch: keep old center
        }
        ((float4*)(out + c * DIM))[lane] = o;
    }
}

// ---------------------------------------------------------------------------
// kernel_launch: graph-capturable, allocation-free, deterministic.
// Inputs (metadata order): x[NP*DIM] f32, y[NP] int64/int32, centers[NC*DIM] f32,
// counter[1] f32. Output: new centers [NC*DIM] f32.
// ---------------------------------------------------------------------------
extern "C" void kernel_launch(void* const* d_in, const int* in_sizes, int n_in,
                              void* d_out, int out_size) {
    const float* x       = (const float*)d_in[0];
    const int*   y32     = (const int*)d_in[1];
    const float* centers = (const float*)d_in[2];
    const float* counter = (const float*)d_in[3];
    float*       out     = (float*)d_out;

    detect_zero_kernel<<<(NC + 255) / 256, 256>>>(y32);
    hist_kernel<<<128, 256>>>(y32);
    scan_kernel<<<1, 1024>>>();
    scatter_kernel<<<512, 256>>>(y32);
    mean_kernel<<<NC, 256>>>(x, centers, counter, out);
}

// round 2
// speedup vs baseline: 1.0168x; 1.0168x over previous
#include <cuda_runtime.h>

#define NP  500000
#define NC  1000
#define DIM 128
#define NB  256                       // partition blocks for counting sort
#define CH  ((NP + NB - 1) / NB)      // 1954 points per block chunk

// Scratch (no allocations allowed -> __device__ globals)
__device__ int g_is64;
__device__ int g_counts[NC];
__device__ int g_offsets[NC];
__device__ int g_bh[NB * NC];         // per-block histogram, block-major
__device__ int g_bb[NB * NC];         // per-(block,class) scatter base
__device__ int g_sorted[NP];

// ---------------------------------------------------------------------------
// Kernel 0: probe y dtype (int64 vs int32). If y is int64 (LE), every odd
// 32-bit word of the first 256 words is 0 (classes < 1000). For int32 input,
// 128 consecutive odd words all zero has probability ~1000^-128.
// ---------------------------------------------------------------------------
__global__ void detect_kernel(const int* __restrict__ y32) {
    if (threadIdx.x == 0) {
        int all0 = 1;
        #pragma unroll
        for (int i = 1; i < 256; i += 2) all0 &= (y32[i] == 0);
        g_is64 = all0;  // 1 -> stride-2 int32 reads (low word of int64)
    }
}

// ---------------------------------------------------------------------------
// Kernel 1: per-block histogram over a contiguous chunk, privatized in smem.
// Writes its row of g_bh (block-major -> fully coalesced, no zeroing needed).
// ---------------------------------------------------------------------------
__global__ void __launch_bounds__(256) blockhist_kernel(const int* __restrict__ y32) {
    __shared__ int h[NC];
    for (int c = threadIdx.x; c < NC; c += 256) h[c] = 0;
    __syncthreads();
    const int shift = g_is64;
    const int b     = blockIdx.x;
    const int start = b * CH;
    const int end   = (start + CH < NP) ? start + CH : NP;
    for (int i = start + threadIdx.x; i < end; i += 256)
        atomicAdd(&h[y32[i << shift]], 1);
    __syncthreads();
    for (int c = threadIdx.x; c < NC; c += 256)
        g_bh[b * NC + c] = h[c];
}

// ---------------------------------------------------------------------------
// Kernel 2: single block. (a) per-class totals (coalesced column reads),
// (b) Hillis-Steele exclusive scan -> class offsets, (c) per-class serial
// prefix over blocks -> per-(block,class) base addresses. All deterministic.
// ---------------------------------------------------------------------------
__global__ void scan_kernel() {
    __shared__ int sh[1024];
    const int t = threadIdx.x;

    int total = 0;
    if (t < NC) {
        #pragma unroll 8
        for (int b = 0; b < NB; b++) total += g_bh[b * NC + t];
    }
    sh[t] = (t < NC) ? total : 0;
    __syncthreads();
    for (int off = 1; off < 1024; off <<= 1) {
        int add = (t >= off) ? sh[t - off] : 0;
        __syncthreads();
        sh[t] += add;
        __syncthreads();
    }
    if (t < NC) {
        int excl = sh[t] - total;
        g_counts[t]  = total;
        g_offsets[t] = excl;
        int run = excl;
        #pragma unroll 4
        for (int b = 0; b < NB; b++) {
            int v = g_bh[b * NC + t];
            g_bb[b * NC + t] = run;
            run += v;
        }
    }
}

// ---------------------------------------------------------------------------
// Kernel 3: scatter using SHARED-MEMORY cursors seeded from g_bb.
// Zero global atomics -> no L2 atomic serialization.
// ---------------------------------------------------------------------------
__global__ void __launch_bounds__(256) scatter_kernel(const int* __restrict__ y32) {
    __shared__ int cur[NC];
    const int b = blockIdx.x;
    for (int c = threadIdx.x; c < NC; c += 256)
        cur[c] = g_bb[b * NC + c];
    __syncthreads();
    const int shift = g_is64;
    const int start = b * CH;
    const int end   = (start + CH < NP) ? start + CH : NP;
    for (int i = start + threadIdx.x; i < end; i += 256) {
        int c   = y32[i << shift];
        int pos = atomicAdd(&cur[c], 1);
        g_sorted[pos] = i;
    }
}

// ---------------------------------------------------------------------------
// Kernel 4: one block per class. 8 row-groups x 32 lanes; each lane owns 4
// dims (float4). Rows are 512B contiguous -> fully coalesced. 4 rows in
// flight per thread for MLP. Reduce groups through shared, then CMA update.
// ---------------------------------------------------------------------------
__global__ void __launch_bounds__(256) mean_kernel(
    const float* __restrict__ x,
    const float* __restrict__ centers,
    const float* __restrict__ counter,
    float*       __restrict__ out)
{
    const int c    = blockIdx.x;
    const int cnt  = g_counts[c];
    const int off  = g_offsets[c];
    const int lane = threadIdx.x & 31;
    const int grp  = threadIdx.x >> 5;

    float4 acc = make_float4(0.f, 0.f, 0.f, 0.f);

    int r = grp;
    for (; r + 24 < cnt; r += 32) {
        int i0 = g_sorted[off + r];
        int i1 = g_sorted[off + r + 8];
        int i2 = g_sorted[off + r + 16];
        int i3 = g_sorted[off + r + 24];
        float4 v0 = ((const float4*)(x + (size_t)i0 * DIM))[lane];
        float4 v1 = ((const float4*)(x + (size_t)i1 * DIM))[lane];
        float4 v2 = ((const float4*)(x + (size_t)i2 * DIM))[lane];
        float4 v3 = ((const float4*)(x + (size_t)i3 * DIM))[lane];
        acc.x += v0.x + v1.x + v2.x + v3.x;
        acc.y += v0.y + v1.y + v2.y + v3.y;
        acc.z += v0.z + v1.z + v2.z + v3.z;
        acc.w += v0.w + v1.w + v2.w + v3.w;
    }
    for (; r < cnt; r += 8) {
        int i = g_sorted[off + r];
        float4 v = ((const float4*)(x + (size_t)i * DIM))[lane];
        acc.x += v.x; acc.y += v.y; acc.z += v.z; acc.w += v.w;
    }

    __shared__ float4 sh[8][32];
    sh[grp][lane] = acc;
    __syncthreads();

    if (grp == 0) {
        float4 s = sh[0][lane];
        #pragma unroll
        for (int g = 1; g < 8; g++) {
            float4 v = sh[g][lane];
            s.x += v.x; s.y += v.y; s.z += v.z; s.w += v.w;
        }
        float4 cv = ((const float4*)(centers + c * DIM))[lane];
        float4 o;
        if (cnt > 0) {
            float ctr = counter[0];
            float inv = 1.0f / (ctr + 1.0f);
            float rn  = 1.0f / (float)cnt;
            o.x = (s.x * rn + cv.x * ctr) * inv;
            o.y = (s.y * rn + cv.y * ctr) * inv;
            o.z = (s.z * rn + cv.z * ctr) * inv;
            o.w = (s.w * rn + cv.w * ctr) * inv;
        } else {
            o = cv;  // class absent from batch: keep old center
        }
        ((float4*)(out + c * DIM))[lane] = o;
    }
}

// ---------------------------------------------------------------------------
// kernel_launch: graph-capturable, allocation-free, deterministic.
// Inputs (metadata order): x[NP*DIM] f32, y[NP] int64/int32, centers[NC*DIM]
// f32, counter[1] f32. Output: new centers [NC*DIM] f32.
// ---------------------------------------------------------------------------
extern "C" void kernel_launch(void* const* d_in, const int* in_sizes, int n_in,
                              void* d_out, int out_size) {
    const float* x       = (const float*)d_in[0];
    const int*   y32     = (const int*)d_in[1];
    const float* centers = (const float*)d_in[2];
    const float* counter = (const float*)d_in[3];
    float*       out     = (float*)d_out;

    detect_kernel<<<1, 32>>>(y32);
    blockhist_kernel<<<NB, 256>>>(y32);
    scan_kernel<<<1, 1024>>>();
    scatter_kernel<<<NB, 256>>>(y32);
    mean_kernel<<<NC, 256>>>(x, centers, counter, out);
}

// round 3
// speedup vs baseline: 1.4436x; 1.4197x over previous
#include <cuda_runtime.h>

#define NP  500000
#define NC  1000
#define DIM 128
#define NB  256                       // partition blocks for counting sort
#define CH  ((NP + NB - 1) / NB)      // 1954 points per block chunk
#define NQ  4                         // quarters for parallel prefix
#define QB  (NB / NQ)                 // 64 blocks per quarter

// Scratch (no allocations allowed -> __device__ globals)
__device__ int g_counts[NC];
__device__ int g_offsets[NC];
__device__ int g_bh[NB * NC];         // per-block histogram, block-major
__device__ int g_qsum[NQ * NC];       // per-(quarter,class) partial sums
__device__ int g_bb[NB * NC];         // per-(block,class) scatter base
__device__ int g_sorted[NP];

// ---------------------------------------------------------------------------
// In-block dtype probe: y int64 (LE) => all odd 32-bit words of the first 256
// words are zero (classes < 1000). P(false positive | int32) ~ 1000^-128.
// 128 lanes check one odd word each; result broadcast via shared.
// ---------------------------------------------------------------------------
__device__ __forceinline__ int probe_is64(const int* __restrict__ y32, int* sflag) {
    if (threadIdx.x < 128) {
        int nz = (y32[2 * threadIdx.x + 1] != 0);
        if (threadIdx.x == 0) *sflag = 0;
        __syncwarp(0xFFFFFFFF);
        // warp-level OR then atomic into shared (4 warps participate)
        unsigned any = __ballot_sync(0xFFFFFFFF, nz);
        if ((threadIdx.x & 31) == 0 && any) atomicOr(sflag, 1);
    }
    __syncthreads();
    return (*sflag == 0) ? 1 : 0;   // no nonzero odd words -> int64
}

// ---------------------------------------------------------------------------
// Kernel 1: per-block histogram over a contiguous chunk, privatized in smem.
// Writes its row of g_bh (block-major -> fully coalesced).
// ---------------------------------------------------------------------------
__global__ void __launch_bounds__(256) blockhist_kernel(const int* __restrict__ y32) {
    __shared__ int h[NC];
    __shared__ int sflag;
    const int shift = probe_is64(y32, &sflag);
    for (int c = threadIdx.x; c < NC; c += 256) h[c] = 0;
    __syncthreads();
    const int b     = blockIdx.x;
    const int start = b * CH;
    const int end   = (start + CH < NP) ? start + CH : NP;
    for (int i = start + threadIdx.x; i < end; i += 256)
        atomicAdd(&h[y32[i << shift]], 1);
    __syncthreads();
    for (int c = threadIdx.x; c < NC; c += 256)
        g_bh[b * NC + c] = h[c];
}

// ---------------------------------------------------------------------------
// Kernel 2: quarter partial sums. thread -> (class c, quarter q); sums its 64
// block-hist entries (coalesced: consecutive threads = consecutive classes).
// 32 blocks x 128 threads = 4096 threads covering 1000 classes x 4 quarters.
// ---------------------------------------------------------------------------
__global__ void __launch_bounds__(128) totals_kernel() {
    const int g = blockIdx.x * 128 + threadIdx.x;
    if (g >= NQ * NC) return;
    const int c = g % NC;
    const int q = g / NC;
    int s = 0;
    #pragma unroll 8
    for (int b = q * QB; b < q * QB + QB; b++) s += g_bh[b * NC + c];
    g_qsum[q * NC + c] = s;
}

// ---------------------------------------------------------------------------
// Kernel 3: single block: per-class totals (4 coalesced loads) + Hillis-Steele
// exclusive scan -> class offsets + counts.
// ---------------------------------------------------------------------------
__global__ void scan_kernel() {
    __shared__ int sh[1024];
    const int t = threadIdx.x;
    int total = 0;
    if (t < NC) {
        #pragma unroll
        for (int q = 0; q < NQ; q++) total += g_qsum[q * NC + t];
    }
    sh[t] = (t < NC) ? total : 0;
    __syncthreads();
    for (int off = 1; off < 1024; off <<= 1) {
        int add = (t >= off) ? sh[t - off] : 0;
        __syncthreads();
        sh[t] += add;
        __syncthreads();
    }
    if (t < NC) {
        g_counts[t]  = total;
        g_offsets[t] = sh[t] - total;
    }
}

// ---------------------------------------------------------------------------
// Kernel 4: per-(block,class) bases. thread -> (class c, quarter q); seeds
// from class offset + earlier quarter sums, then serial prefix over only 64
// blocks (register-carried, loads prefetchable under unroll).
// ---------------------------------------------------------------------------
__global__ void __launch_bounds__(128) bases_kernel() {
    const int g = blockIdx.x * 128 + threadIdx.x;
    if (g >= NQ * NC) return;
    const int c = g % NC;
    const int q = g / NC;
    int run = g_offsets[c];
    #pragma unroll
    for (int p = 0; p < NQ; p++) if (p < q) run += g_qsum[p * NC + c];
    #pragma unroll 8
    for (int b = q * QB; b < q * QB + QB; b++) {
        int v = g_bh[b * NC + c];
        g_bb[b * NC + c] = run;
        run += v;
    }
}

// ---------------------------------------------------------------------------
// Kernel 5: scatter using SHARED-MEMORY cursors seeded from g_bb.
// Zero global atomics.
// ---------------------------------------------------------------------------
__global__ void __launch_bounds__(256) scatter_kernel(const int* __restrict__ y32) {
    __shared__ int cur[NC];
    __shared__ int sflag;
    const int shift = probe_is64(y32, &sflag);
    const int b = blockIdx.x;
    for (int c = threadIdx.x; c < NC; c += 256)
        cur[c] = g_bb[b * NC + c];
    __syncthreads();
    const int start = b * CH;
    const int end   = (start + CH < NP) ? start + CH : NP;
    for (int i = start + threadIdx.x; i < end; i += 256) {
        int c   = y32[i << shift];
        int pos = atomicAdd(&cur[c], 1);
        g_sorted[pos] = i;
    }
}

// ---------------------------------------------------------------------------
// Kernel 6: one block per class. 8 warps; warp = row-group, lane owns 4 dims
// (float4, 512B coalesced rows). 8 rows in flight per warp (28KB/SM in-flight
// -> saturates HBM per Little's law), 4-deep mid-tail, scalar final tail.
// Streaming loads (x is read-once). Reduce through shared, CMA update.
// ---------------------------------------------------------------------------
__global__ void __launch_bounds__(256) mean_kernel(
    const float* __restrict__ x,
    const float* __restrict__ centers,
    const float* __restrict__ counter,
    float*       __restrict__ out)
{
    const int c    = blockIdx.x;
    const int cnt  = g_counts[c];
    const int off  = g_offsets[c];
    const int lane = threadIdx.x & 31;
    const int grp  = threadIdx.x >> 5;

    float4 acc = make_float4(0.f, 0.f, 0.f, 0.f);

    int r = grp;
    // main loop: 8 rows in flight per warp
    for (; r + 56 < cnt; r += 64) {
        int idx[8];
        #pragma unroll
        for (int k = 0; k < 8; k++) idx[k] = g_sorted[off + r + 8 * k];
        #pragma unroll
        for (int k = 0; k < 8; k++) {
            float4 v = __ldcs(&((const float4*)(x + (size_t)idx[k] * DIM))[lane]);
            acc.x += v.x; acc.y += v.y; acc.z += v.z; acc.w += v.w;
        }
    }
    // mid tail: 4 rows in flight
    for (; r + 24 < cnt; r += 32) {
        int idx[4];
        #pragma unroll
        for (int k = 0; k < 4; k++) idx[k] = g_sorted[off + r + 8 * k];
        #pragma unroll
        for (int k = 0; k < 4; k++) {
            float4 v = __ldcs(&((const float4*)(x + (size_t)idx[k] * DIM))[lane]);
            acc.x += v.x; acc.y += v.y; acc.z += v.z; acc.w += v.w;
        }
    }
    // final tail
    for (; r < cnt; r += 8) {
        int i = g_sorted[off + r];
        float4 v = __ldcs(&((const float4*)(x + (size_t)i * DIM))[lane]);
        acc.x += v.x; acc.y += v.y; acc.z += v.z; acc.w += v.w;
    }

    __shared__ float4 sh[8][32];
    sh[grp][lane] = acc;
    __syncthreads();

    if (grp == 0) {
        float4 s = sh[0][lane];
        #pragma unroll
        for (int g = 1; g < 8; g++) {
            float4 v = sh[g][lane];
            s.x += v.x; s.y += v.y; s.z += v.z; s.w += v.w;
        }
        float4 cv = ((const float4*)(centers + c * DIM))[lane];
        float4 o;
        if (cnt > 0) {
            float ctr = counter[0];
            float inv = 1.0f / (ctr + 1.0f);
            float rn  = 1.0f / (float)cnt;
            o.x = (s.x * rn + cv.x * ctr) * inv;
            o.y = (s.y * rn + cv.y * ctr) * inv;
            o.z = (s.z * rn + cv.z * ctr) * inv;
            o.w = (s.w * rn + cv.w * ctr) * inv;
        } else {
            o = cv;  // class absent from batch: keep old center
        }
        ((float4*)(out + c * DIM))[lane] = o;
    }
}

// ---------------------------------------------------------------------------
// kernel_launch: graph-capturable, allocation-free, deterministic.
// Inputs (metadata order): x[NP*DIM] f32, y[NP] int64/int32, centers[NC*DIM]
// f32, counter[1] f32. Output: new centers [NC*DIM] f32.
// ---------------------------------------------------------------------------
extern "C" void kernel_launch(void* const* d_in, const int* in_sizes, int n_in,
                              void* d_out, int out_size) {
    const float* x       = (const float*)d_in[0];
    const int*   y32     = (const int*)d_in[1];
    const float* centers = (const float*)d_in[2];
    const float* counter = (const float*)d_in[3];
    float*       out     = (float*)d_out;

    blockhist_kernel<<<NB, 256>>>(y32);
    totals_kernel<<<(NQ * NC + 127) / 128, 128>>>();
    scan_kernel<<<1, 1024>>>();
    bases_kernel<<<(NQ * NC + 127) / 128, 128>>>();
    scatter_kernel<<<NB, 256>>>(y32);
    mean_kernel<<<NC, 256>>>(x, centers, counter, out);
}

// round 4
// speedup vs baseline: 1.5410x; 1.0675x over previous
#include <cuda_runtime.h>

#define NP  500000
#define NC  1000
#define DIM 128
#define NB  256                       // partition blocks for counting sort
#define CH  ((NP + NB - 1) / NB)      // 1954 points per block chunk
#define NQ  16                        // quarter-groups for parallel prefix
#define QB  (NB / NQ)                 // 16 blocks per group

// Scratch (no allocations allowed -> __device__ globals)
__device__ int g_counts[NC];
__device__ int g_offsets[NC];
__device__ int g_bh[NB * NC];         // per-block histogram, block-major
__device__ int g_qsum[NQ * NC];       // per-(group,class) partial sums
__device__ int g_qpre[NQ * NC];       // per-(group,class) running base
__device__ int g_bb[NB * NC];         // per-(block,class) scatter base
__device__ int g_sorted[NP];

// ---------------------------------------------------------------------------
// In-block dtype probe: y int64 (LE) => all odd 32-bit words of the first 256
// words are zero (classes < 1000). P(false positive | int32) ~ 1000^-128.
// ---------------------------------------------------------------------------
__device__ __forceinline__ int probe_is64(const int* __restrict__ y32, int* sflag) {
    if (threadIdx.x == 0) *sflag = 0;
    __syncthreads();
    if (threadIdx.x < 128) {
        int nz = (y32[2 * threadIdx.x + 1] != 0);
        unsigned any = __ballot_sync(0xFFFFFFFF, nz);
        if ((threadIdx.x & 31) == 0 && any) atomicOr(sflag, 1);
    }
    __syncthreads();
    return (*sflag == 0) ? 1 : 0;   // no nonzero odd words -> int64
}

// ---------------------------------------------------------------------------
// Kernel 1: per-block histogram over a contiguous chunk, privatized in smem.
// Writes its row of g_bh (block-major -> fully coalesced).
// ---------------------------------------------------------------------------
__global__ void __launch_bounds__(256) blockhist_kernel(const int* __restrict__ y32) {
    __shared__ int h[NC];
    __shared__ int sflag;
    const int shift = probe_is64(y32, &sflag);
    for (int c = threadIdx.x; c < NC; c += 256) h[c] = 0;
    __syncthreads();
    const int b     = blockIdx.x;
    const int start = b * CH;
    const int end   = (start + CH < NP) ? start + CH : NP;
    for (int i = start + threadIdx.x; i < end; i += 256)
        atomicAdd(&h[y32[i << shift]], 1);
    __syncthreads();
    for (int c = threadIdx.x; c < NC; c += 256)
        g_bh[b * NC + c] = h[c];
}

// ---------------------------------------------------------------------------
// Kernel 2: group partial sums. thread -> (class c, group q); sums its 16
// block-hist entries (coalesced: consecutive threads = consecutive classes).
// 16000 threads -> latency fully overlapped.
// ---------------------------------------------------------------------------
__global__ void __launch_bounds__(256) totals_kernel() {
    const int g = blockIdx.x * 256 + threadIdx.x;
    if (g >= NQ * NC) return;
    const int c = g % NC;
    const int q = g / NC;
    int s = 0;
    #pragma unroll
    for (int b = q * QB; b < q * QB + QB; b++) s += g_bh[b * NC + c];
    g_qsum[q * NC + c] = s;
}

// ---------------------------------------------------------------------------
// Kernel 3: single block. Per-class totals (16 coalesced loads, L2-hot) +
// Hillis-Steele exclusive scan -> class offsets, plus per-group running bases
// g_qpre so bases_kernel needs no re-derivation.
// ---------------------------------------------------------------------------
__global__ void scan_kernel() {
    __shared__ int sh[1024];
    const int t = threadIdx.x;
    int qs[NQ];
    int total = 0;
    if (t < NC) {
        #pragma unroll
        for (int q = 0; q < NQ; q++) { qs[q] = g_qsum[q * NC + t]; total += qs[q]; }
    }
    sh[t] = (t < NC) ? total : 0;
    __syncthreads();
    for (int off = 1; off < 1024; off <<= 1) {
        int add = (t >= off) ? sh[t - off] : 0;
        __syncthreads();
        sh[t] += add;
        __syncthreads();
    }
    if (t < NC) {
        int excl = sh[t] - total;
        g_counts[t]  = total;
        g_offsets[t] = excl;
        int run = excl;
        #pragma unroll
        for (int q = 0; q < NQ; q++) { g_qpre[q * NC + t] = run; run += qs[q]; }
    }
}

// ---------------------------------------------------------------------------
// Kernel 4: per-(block,class) bases. thread -> (class c, group q); seeds from
// g_qpre, serial prefix over only 16 blocks. 16000 threads.
// ---------------------------------------------------------------------------
__global__ void __launch_bounds__(256) bases_kernel() {
    const int g = blockIdx.x * 256 + threadIdx.x;
    if (g >= NQ * NC) return;
    const int c = g % NC;
    const int q = g / NC;
    int run = g_qpre[q * NC + c];
    #pragma unroll
    for (int b = q * QB; b < q * QB + QB; b++) {
        int v = g_bh[b * NC + c];
        g_bb[b * NC + c] = run;
        run += v;
    }
}

// ---------------------------------------------------------------------------
// Kernel 5: scatter using SHARED-MEMORY cursors seeded from g_bb.
// Zero global atomics.
// ---------------------------------------------------------------------------
__global__ void __launch_bounds__(256) scatter_kernel(const int* __restrict__ y32) {
    __shared__ int cur[NC];
    __shared__ int sflag;
    const int shift = probe_is64(y32, &sflag);
    const int b = blockIdx.x;
    for (int c = threadIdx.x; c < NC; c += 256)
        cur[c] = g_bb[b * NC + c];
    __syncthreads();
    const int start = b * CH;
    const int end   = (start + CH < NP) ? start + CH : NP;
    for (int i = start + threadIdx.x; i < end; i += 256) {
        int c   = y32[i << shift];
        int pos = atomicAdd(&cur[c], 1);
        g_sorted[pos] = i;
    }
}

// ---------------------------------------------------------------------------
// Kernel 6: one block per class. 8 warps; warp = row-group, lane owns 4 dims
// (float4, 512B coalesced rows). 8 rows in flight per warp, 4-deep mid-tail,
// scalar final tail. Streaming loads. Reduce through shared, CMA update.
// ---------------------------------------------------------------------------
__global__ void __launch_bounds__(256) mean_kernel(
    const float* __restrict__ x,
    const float* __restrict__ centers,
    const float* __restrict__ counter,
    float*       __restrict__ out)
{
    const int c    = blockIdx.x;
    const int cnt  = g_counts[c];
    const int off  = g_offsets[c];
    const int lane = threadIdx.x & 31;
    const int grp  = threadIdx.x >> 5;

    float4 acc = make_float4(0.f, 0.f, 0.f, 0.f);

    int r = grp;
    for (; r + 56 < cnt; r += 64) {
        int idx[8];
        #pragma unroll
        for (int k = 0; k < 8; k++) idx[k] = g_sorted[off + r + 8 * k];
        #pragma unroll
        for (int k = 0; k < 8; k++) {
            float4 v = __ldcs(&((const float4*)(x + (size_t)idx[k] * DIM))[lane]);
            acc.x += v.x; acc.y += v.y; acc.z += v.z; acc.w += v.w;
        }
    }
    for (; r + 24 < cnt; r += 32) {
        int idx[4];
        #pragma unroll
        for (int k = 0; k < 4; k++) idx[k] = g_sorted[off + r + 8 * k];
        #pragma unroll
        for (int k = 0; k < 4; k++) {
            float4 v = __ldcs(&((const float4*)(x + (size_t)idx[k] * DIM))[lane]);
            acc.x += v.x; acc.y += v.y; acc.z += v.z; acc.w += v.w;
        }
    }
    for (; r < cnt; r += 8) {
        int i = g_sorted[off + r];
        float4 v = __ldcs(&((const float4*)(x + (size_t)i * DIM))[lane]);
        acc.x += v.x; acc.y += v.y; acc.z += v.z; acc.w += v.w;
    }

    __shared__ float4 sh[8][32];
    sh[grp][lane] = acc;
    __syncthreads();

    if (grp == 0) {
        float4 s = sh[0][lane];
        #pragma unroll
        for (int g = 1; g < 8; g++) {
            float4 v = sh[g][lane];
            s.x += v.x; s.y += v.y; s.z += v.z; s.w += v.w;
        }
        float4 cv = ((const float4*)(centers + c * DIM))[lane];
        float4 o;
        if (cnt > 0) {
            float ctr = counter[0];
            float inv = 1.0f / (ctr + 1.0f);
            float rn  = 1.0f / (float)cnt;
            o.x = (s.x * rn + cv.x * ctr) * inv;
            o.y = (s.y * rn + cv.y * ctr) * inv;
            o.z = (s.z * rn + cv.z * ctr) * inv;
            o.w = (s.w * rn + cv.w * ctr) * inv;
        } else {
            o = cv;  // class absent from batch: keep old center
        }
        ((float4*)(out + c * DIM))[lane] = o;
    }
}

// ---------------------------------------------------------------------------
// kernel_launch: graph-capturable, allocation-free, deterministic.
// Inputs (metadata order): x[NP*DIM] f32, y[NP] int64/int32, centers[NC*DIM]
// f32, counter[1] f32. Output: new centers [NC*DIM] f32.
// ---------------------------------------------------------------------------
extern "C" void kernel_launch(void* const* d_in, const int* in_sizes, int n_in,
                              void* d_out, int out_size) {
    const float* x       = (const float*)d_in[0];
    const int*   y32     = (const int*)d_in[1];
    const float* centers = (const float*)d_in[2];
    const float* counter = (const float*)d_in[3];
    float*       out     = (float*)d_out;

    blockhist_kernel<<<NB, 256>>>(y32);
    totals_kernel<<<(NQ * NC + 255) / 256, 256>>>();
    scan_kernel<<<1, 1024>>>();
    bases_kernel<<<(NQ * NC + 255) / 256, 256>>>();
    scatter_kernel<<<NB, 256>>>(y32);
    mean_kernel<<<NC, 256>>>(x, centers, counter, out);
}

// round 5
// speedup vs baseline: 1.6464x; 1.0684x over previous
#include <cuda_runtime.h>

#define NP  500000
#define NC  1000
#define DIM 128
#define NB  256                       // partition blocks for counting sort
#define CH  ((NP + NB - 1) / NB)      // 1954 points per block chunk

// Scratch (no allocations allowed -> __device__ globals)
__device__ int g_counts[NC];
__device__ int g_offsets[NC];
__device__ int g_bh[NB * NC];         // per-block histogram, block-major
__device__ int g_bb[NB * NC];         // per-(block,class) LOCAL base (no class offset)
__device__ int g_sorted[NP];

// ---------------------------------------------------------------------------
// In-block dtype probe: y int64 (LE) => all odd 32-bit words of the first 256
// words are zero (classes < 1000). P(false positive | int32) ~ 1000^-128.
// ---------------------------------------------------------------------------
__device__ __forceinline__ int probe_is64(const int* __restrict__ y32, int* sflag) {
    if (threadIdx.x == 0) *sflag = 0;
    __syncthreads();
    if (threadIdx.x < 128) {
        int nz = (y32[2 * threadIdx.x + 1] != 0);
        unsigned any = __ballot_sync(0xFFFFFFFF, nz);
        if ((threadIdx.x & 31) == 0 && any) atomicOr(sflag, 1);
    }
    __syncthreads();
    return (*sflag == 0) ? 1 : 0;   // no nonzero odd words -> int64
}

// ---------------------------------------------------------------------------
// Kernel 1: per-block histogram over a contiguous chunk, privatized in smem.
// 512 threads (more warps to hide smem-atomic latency). Coalesced row write.
// ---------------------------------------------------------------------------
__global__ void __launch_bounds__(512) blockhist_kernel(const int* __restrict__ y32) {
    __shared__ int h[NC];
    __shared__ int sflag;
    const int shift = probe_is64(y32, &sflag);
    for (int c = threadIdx.x; c < NC; c += 512) h[c] = 0;
    __syncthreads();
    const int b     = blockIdx.x;
    const int start = b * CH;
    const int end   = (start + CH < NP) ? start + CH : NP;
    for (int i = start + threadIdx.x; i < end; i += 512)
        atomicAdd(&h[y32[i << shift]], 1);
    __syncthreads();
    for (int c = threadIdx.x; c < NC; c += 512)
        g_bh[b * NC + c] = h[c];
}

// ---------------------------------------------------------------------------
// Kernel 2: block-per-class parallel scan over the NB=256 block counts.
// Thread t loads g_bh[t][c] (single L2 round-trip, no serial chain), shfl
// warp-scan + cross-warp combine -> local exclusive base g_bb[t][c] and the
// class total g_counts[c]. Replaces totals/bases/qpre entirely.
// ---------------------------------------------------------------------------
__global__ void __launch_bounds__(NB) blockscan_kernel() {
    const int c    = blockIdx.x;
    const int t    = threadIdx.x;          // = block index b
    const int lane = t & 31;
    const int w    = t >> 5;               // 8 warps

    int v = g_bh[t * NC + c];

    // warp inclusive scan
    int s = v;
    #pragma unroll
    for (int o = 1; o < 32; o <<= 1) {
        int n = __shfl_up_sync(0xFFFFFFFF, s, o);
        if (lane >= o) s += n;
    }

    __shared__ int wsum[8];
    __shared__ int wbase[8];
    if (lane == 31) wsum[w] = s;
    __syncthreads();

    if (w == 0 && lane < 8) {
        int ws = wsum[lane];
        int sc = ws;
        #pragma unroll
        for (int o = 1; o < 8; o <<= 1) {
            int n = __shfl_up_sync(0x000000FF, sc, o);
            if (lane >= o) sc += n;
        }
        wbase[lane] = sc - ws;             // exclusive warp base
        if (lane == 7) g_counts[c] = sc;   // class total
    }
    __syncthreads();

    g_bb[t * NC + c] = (s - v) + wbase[w]; // local exclusive prefix
}

// ---------------------------------------------------------------------------
// Kernel 3: single block, bare Hillis-Steele exclusive scan of class totals.
// ---------------------------------------------------------------------------
__global__ void scan_kernel() {
    __shared__ int sh[1024];
    const int t = threadIdx.x;
    int total = (t < NC) ? g_counts[t] : 0;
    sh[t] = total;
    __syncthreads();
    for (int off = 1; off < 1024; off <<= 1) {
        int add = (t >= off) ? sh[t - off] : 0;
        __syncthreads();
        sh[t] += add;
        __syncthreads();
    }
    if (t < NC) g_offsets[t] = sh[t] - total;
}

// ---------------------------------------------------------------------------
// Kernel 4: scatter using SHARED-MEMORY cursors seeded from local base +
// class offset (both coalesced). Zero global atomics. 512 threads.
// ---------------------------------------------------------------------------
__global__ void __launch_bounds__(512) scatter_kernel(const int* __restrict__ y32) {
    __shared__ int cur[NC];
    __shared__ int sflag;
    const int shift = probe_is64(y32, &sflag);
    const int b = blockIdx.x;
    for (int c = threadIdx.x; c < NC; c += 512)
        cur[c] = g_bb[b * NC + c] + g_offsets[c];
    __syncthreads();
    const int start = b * CH;
    const int end   = (start + CH < NP) ? start + CH : NP;
    for (int i = start + threadIdx.x; i < end; i += 512) {
        int c   = y32[i << shift];
        int pos = atomicAdd(&cur[c], 1);
        g_sorted[pos] = i;
    }
}

// ---------------------------------------------------------------------------
// Kernel 5: one block per class. 8 warps; warp = row-group, lane owns 4 dims
// (float4, 512B coalesced rows). 8 rows in flight per warp, 4-deep mid-tail,
// scalar final tail. Streaming loads. Reduce through shared, CMA update.
// ---------------------------------------------------------------------------
__global__ void __launch_bounds__(256) mean_kernel(
    const float* __restrict__ x,
    const float* __restrict__ centers,
    const float* __restrict__ counter,
    float*       __restrict__ out)
{
    const int c    = blockIdx.x;
    const int cnt  = g_counts[c];
    const int off  = g_offsets[c];
    const int lane = threadIdx.x & 31;
    const int grp  = threadIdx.x >> 5;

    float4 acc = make_float4(0.f, 0.f, 0.f, 0.f);

    int r = grp;
    for (; r + 56 < cnt; r += 64) {
        int idx[8];
        #pragma unroll
        for (int k = 0; k < 8; k++) idx[k] = g_sorted[off + r + 8 * k];
        #pragma unroll
        for (int k = 0; k < 8; k++) {
            float4 v = __ldcs(&((const float4*)(x + (size_t)idx[k] * DIM))[lane]);
            acc.x += v.x; acc.y += v.y; acc.z += v.z; acc.w += v.w;
        }
    }
    for (; r + 24 < cnt; r += 32) {
        int idx[4];
        #pragma unroll
        for (int k = 0; k < 4; k++) idx[k] = g_sorted[off + r + 8 * k];
        #pragma unroll
        for (int k = 0; k < 4; k++) {
            float4 v = __ldcs(&((const float4*)(x + (size_t)idx[k] * DIM))[lane]);
            acc.x += v.x; acc.y += v.y; acc.z += v.z; acc.w += v.w;
        }
    }
    for (; r < cnt; r += 8) {
        int i = g_sorted[off + r];
        float4 v = __ldcs(&((const float4*)(x + (size_t)i * DIM))[lane]);
        acc.x += v.x; acc.y += v.y; acc.z += v.z; acc.w += v.w;
    }

    __shared__ float4 sh[8][32];
    sh[grp][lane] = acc;
    __syncthreads();

    if (grp == 0) {
        float4 s = sh[0][lane];
        #pragma unroll
        for (int g = 1; g < 8; g++) {
            float4 v = sh[g][lane];
            s.x += v.x; s.y += v.y; s.z += v.z; s.w += v.w;
        }
        float4 cv = ((const float4*)(centers + c * DIM))[lane];
        float4 o;
        if (cnt > 0) {
            float ctr = counter[0];
            float inv = 1.0f / (ctr + 1.0f);
            float rn  = 1.0f / (float)cnt;
            o.x = (s.x * rn + cv.x * ctr) * inv;
            o.y = (s.y * rn + cv.y * ctr) * inv;
            o.z = (s.z * rn + cv.z * ctr) * inv;
            o.w = (s.w * rn + cv.w * ctr) * inv;
        } else {
            o = cv;  // class absent from batch: keep old center
        }
        ((float4*)(out + c * DIM))[lane] = o;
    }
}

// ---------------------------------------------------------------------------
// kernel_launch: graph-capturable, allocation-free, deterministic.
// Inputs (metadata order): x[NP*DIM] f32, y[NP] int64/int32, centers[NC*DIM]
// f32, counter[1] f32. Output: new centers [NC*DIM] f32.
// ---------------------------------------------------------------------------
extern "C" void kernel_launch(void* const* d_in, const int* in_sizes, int n_in,
                              void* d_out, int out_size) {
    const float* x       = (const float*)d_in[0];
    const int*   y32     = (const int*)d_in[1];
    const float* centers = (const float*)d_in[2];
    const float* counter = (const float*)d_in[3];
    float*       out     = (float*)d_out;

    blockhist_kernel<<<NB, 512>>>(y32);
    blockscan_kernel<<<NC, NB>>>();
    scan_kernel<<<1, 1024>>>();
    scatter_kernel<<<NB, 512>>>(y32);
    mean_kernel<<<NC, 256>>>(x, centers, counter, out);
}